// round 2
// baseline (speedup 1.0000x reference)
#include <cuda_runtime.h>
#include <stdint.h>

#define NT 32768     // tokens
#define DIM 512      // embedding dim
#define NE 8192      // codebook size

#define BM 128
#define BN 128
#define BK 16
#define TM 8
#define TN 8

// ---- scratch (no cudaMalloc allowed) ----
__device__ unsigned long long g_rowmin[NT];            // packed (dist_bits<<32 | col)
__device__ float g_xnorm[NT];
__device__ float g_enorm[NE];
__device__ float g_embedT[(size_t)NE * DIM];           // 16 MB transposed codebook
__device__ float g_rowloss[NT];

__global__ void init_rowmin_kernel() {
    int i = blockIdx.x * blockDim.x + threadIdx.x;
    if (i < NT) g_rowmin[i] = 0xFFFFFFFFFFFFFFFFULL;
}

// per-row squared norm of input, one warp per row
__global__ void xnorm_kernel(const float* __restrict__ x) {
    int row = blockIdx.x * 8 + (threadIdx.x >> 5);
    int lane = threadIdx.x & 31;
    const float4* xr = (const float4*)(x + (size_t)row * DIM);
    float s = 0.f;
    #pragma unroll
    for (int i = lane; i < DIM / 4; i += 32) {
        float4 v = xr[i];
        s += v.x * v.x + v.y * v.y + v.z * v.z + v.w * v.w;
    }
    #pragma unroll
    for (int o = 16; o; o >>= 1) s += __shfl_down_sync(0xffffffffu, s, o);
    if (lane == 0) g_xnorm[row] = s;
}

// per-column squared norm of embed ([DIM, NE] row-major -> coalesced across j)
__global__ void enorm_kernel(const float* __restrict__ e) {
    int j = blockIdx.x * blockDim.x + threadIdx.x;
    if (j >= NE) return;
    float s = 0.f;
    for (int d = 0; d < DIM; ++d) {
        float v = e[(size_t)d * NE + j];
        s += v * v;
    }
    g_enorm[j] = s;
}

// transpose embed [DIM, NE] -> g_embedT [NE, DIM] for coalesced gathers
__global__ void transpose_kernel(const float* __restrict__ e) {
    __shared__ float t[32][33];
    int j0 = blockIdx.x * 32;
    int d0 = blockIdx.y * 32;
    int tx = threadIdx.x, ty = threadIdx.y;  // 32 x 8
    #pragma unroll
    for (int r = 0; r < 32; r += 8)
        t[ty + r][tx] = e[(size_t)(d0 + ty + r) * NE + j0 + tx];
    __syncthreads();
    #pragma unroll
    for (int r = 0; r < 32; r += 8)
        g_embedT[(size_t)(j0 + ty + r) * DIM + d0 + tx] = t[tx][ty + r];
}

// fused GEMM: dist = xnorm - 2*x@E + enorm ; dist store (scalar, coalesced,
// alignment-immune: dist base is at an odd float offset in d_out); row argmin.
// Column ownership is INTERLEAVED: thread tx owns cols {tx + 16*j}, so scalar
// stores of dv[j] across a warp hit consecutive addresses.
__global__ void __launch_bounds__(256) gemm_dist_kernel(
    const float* __restrict__ X, const float* __restrict__ E,
    float* __restrict__ distp)
{
    __shared__ float As[BK][BM];
    __shared__ float Bs[BK][BN];
    __shared__ unsigned long long smin[BM];

    const int tid = threadIdx.x;
    const int browg = blockIdx.y * BM;
    const int bcolg = blockIdx.x * BN;
    const int ty = tid >> 4;       // 0..15
    const int tx = tid & 15;       // 0..15

    if (tid < BM) smin[tid] = 0xFFFFFFFFFFFFFFFFULL;

    float acc[TM][TN];
    #pragma unroll
    for (int i = 0; i < TM; i++)
        #pragma unroll
        for (int j = 0; j < TN; j++) acc[i][j] = 0.f;

    const int arow = tid >> 2;           // 0..63
    const int acol = (tid & 3) * 4;      // 0,4,8,12
    const int brw  = tid >> 5;           // 0..7
    const int bcl  = (tid & 31) * 4;     // 0..124

    for (int k0 = 0; k0 < DIM; k0 += BK) {
        #pragma unroll
        for (int r = 0; r < 2; r++) {
            float4 v = *(const float4*)(X + (size_t)(browg + arow + r * 64) * DIM + k0 + acol);
            As[acol + 0][arow + r * 64] = v.x;
            As[acol + 1][arow + r * 64] = v.y;
            As[acol + 2][arow + r * 64] = v.z;
            As[acol + 3][arow + r * 64] = v.w;
        }
        #pragma unroll
        for (int r = 0; r < 2; r++) {
            float4 v = *(const float4*)(E + (size_t)(k0 + brw + r * 8) * NE + bcolg + bcl);
            *(float4*)&Bs[brw + r * 8][bcl] = v;
        }
        __syncthreads();

        #pragma unroll
        for (int k = 0; k < BK; k++) {
            float a[TM], b[TN];
            #pragma unroll
            for (int i = 0; i < TM; i++) a[i] = As[k][ty * TM + i];
            #pragma unroll
            for (int j = 0; j < TN; j++) b[j] = Bs[k][tx + j * 16];   // interleaved cols
            #pragma unroll
            for (int i = 0; i < TM; i++)
                #pragma unroll
                for (int j = 0; j < TN; j++)
                    acc[i][j] = fmaf(a[i], b[j], acc[i][j]);
        }
        __syncthreads();
    }

    // epilogue: dist values + argmin (first-occurrence tie-break like jnp.argmin)
    #pragma unroll
    for (int i = 0; i < TM; i++) {
        const int row = browg + ty * TM + i;
        const float xn = g_xnorm[row];
        float best = 3.4e38f;
        int bj = NE;
        float* drow = distp ? (distp + (size_t)row * NE + bcolg) : 0;
        #pragma unroll
        for (int j = 0; j < TN; j++) {
            const int col = bcolg + tx + j * 16;
            const float dval = xn - 2.f * acc[i][j] + g_enorm[col];
            if (drow) drow[tx + j * 16] = dval;   // lanes consecutive -> coalesced
            if (dval < best) { best = dval; bj = col; }
        }
        const unsigned long long packed =
            ((unsigned long long)__float_as_uint(best) << 32) | (unsigned)bj;
        atomicMin(&smin[ty * TM + i], packed);
    }
    __syncthreads();
    if (tid < BM) atomicMin(&g_rowmin[browg + tid], smin[tid]);
}

// gather quantize rows (coalesced via transposed codebook), ST output, per-row loss
__global__ void gather_kernel(const float* __restrict__ X,
                              float* __restrict__ qp,
                              float* __restrict__ indp)
{
    const int row = blockIdx.x;
    const int tid = threadIdx.x;   // 128 threads, DIM/4 == 128
    const unsigned long long pk = g_rowmin[row];
    const unsigned ind = (unsigned)(pk & 0xFFFFFFFFu);
    if (indp && tid == 0) indp[row] = (float)ind;

    const float4 q = ((const float4*)(g_embedT + (size_t)ind * DIM))[tid];
    const float4 x = ((const float4*)(X + (size_t)row * DIM))[tid];

    if (qp) {
        float4 o;
        o.x = x.x + (q.x - x.x);
        o.y = x.y + (q.y - x.y);
        o.z = x.z + (q.z - x.z);
        o.w = x.w + (q.w - x.w);
        ((float4*)(qp + (size_t)row * DIM))[tid] = o;
    }

    float dx = x.x - q.x, dy = x.y - q.y, dz = x.z - q.z, dw = x.w - q.w;
    float ls = dx * dx + dy * dy + dz * dz + dw * dw;

    __shared__ float red[128];
    red[tid] = ls;
    __syncthreads();
    #pragma unroll
    for (int s = 64; s; s >>= 1) {
        if (tid < s) red[tid] += red[tid + s];
        __syncthreads();
    }
    if (tid == 0) g_rowloss[row] = red[0];
}

// deterministic final loss reduce
__global__ void loss_kernel(float* __restrict__ lossp) {
    __shared__ float red[512];
    const int tid = threadIdx.x;
    float s = 0.f;
    for (int i = tid; i < NT; i += 512) s += g_rowloss[i];
    red[tid] = s;
    __syncthreads();
    #pragma unroll
    for (int st = 256; st; st >>= 1) {
        if (tid < st) red[tid] += red[tid + st];
        __syncthreads();
    }
    if (tid == 0) *lossp = red[0] * (1.0f / ((float)NT * (float)DIM));
}

extern "C" void kernel_launch(void* const* d_in, const int* in_sizes, int n_in,
                              void* d_out, int out_size) {
    const float* X = (const float*)d_in[0];   // [NT, DIM]
    const float* E = (const float*)d_in[1];   // [DIM, NE]
    float* out = (float*)d_out;

    const long long QN = (long long)NT * DIM;      // 16777216
    const long long DN = (long long)NT * NE;       // 268435456
    const long long OS = (long long)out_size;

    float *qp = 0, *indp = 0, *lossp = 0, *distp = 0;
    if (OS == QN + NT + 1 + DN) {                 // full tuple concat
        qp = out; indp = out + QN; lossp = out + QN + NT; distp = out + QN + NT + 1;
    } else if (OS == QN) {                         // quantize_st only
        qp = out;
    } else if (OS == DN) {                         // dist only
        distp = out;
    } else if (OS == NT) {                         // embed_ind only
        indp = out;
    } else if (OS == 1) {                          // loss only
        lossp = out;
    } else if (OS == QN + NT + 1) {                // tuple without dist
        qp = out; indp = out + QN; lossp = out + QN + NT;
    } else {                                       // unknown: fill concat order, bounded
        if (OS >= QN) qp = out;
        if (OS >= QN + NT) indp = out + QN;
        if (OS >= QN + NT + 1) lossp = out + QN + NT;
        if (OS >= QN + NT + 1 + DN) distp = out + QN + NT + 1;
    }

    init_rowmin_kernel<<<NT / 256, 256>>>();
    xnorm_kernel<<<NT / 8, 256>>>(X);
    enorm_kernel<<<NE / 256, 256>>>(E);
    transpose_kernel<<<dim3(NE / 32, DIM / 32), dim3(32, 8)>>>(E);
    gemm_dist_kernel<<<dim3(NE / BN, NT / BM), 256>>>(X, E, distp);
    gather_kernel<<<NT, 128>>>(X, qp, indp);
    if (lossp) loss_kernel<<<1, 512>>>(lossp);
}

// round 4
// speedup vs baseline: 1.4762x; 1.4762x over previous
#include <cuda_runtime.h>
#include <stdint.h>

#define NT 32768     // tokens
#define DIM 512      // embedding dim
#define NE 8192      // codebook size

#define TILE_M 128
#define TILE_N 128
#define KB 16
#define NSTAGE (DIM / KB)     // 32

// smem (dynamic): [0,1024) smin u64[128]; [1024, +2*40960) stages / dist tile
#define SM_SMIN_OFF 0
#define SM_DATA_OFF 1024
#define STAGE_FLOATS 10240          // 40960 B per stage
#define A_HI 0
#define A_LO 2560                   // 128 rows * pitch 20
#define B_HI 5120
#define B_LO 7680
#define SMEM_TOTAL (1024 + 2 * 40960)

// ---- device scratch ----
__device__ unsigned long long g_rowmin[NT];
__device__ float g_xnorm[NT];
__device__ float g_enorm[NE];
__device__ float g_embedT[(size_t)NE * DIM];   // 16 MB transposed codebook
__device__ float g_rowloss[NT];

__device__ __forceinline__ float tf32_rna(float x) {
    uint32_t r;
    asm("cvt.rna.tf32.f32 %0, %1;" : "=r"(r) : "f"(x));
    return __uint_as_float(r);
}
__device__ __forceinline__ void mma_tf32(float* d, const uint32_t* a, const uint32_t* b) {
    asm volatile("mma.sync.aligned.m16n8k8.row.col.f32.tf32.tf32.f32 "
                 "{%0,%1,%2,%3}, {%4,%5,%6,%7}, {%8,%9}, {%0,%1,%2,%3};"
                 : "+f"(d[0]), "+f"(d[1]), "+f"(d[2]), "+f"(d[3])
                 : "r"(a[0]), "r"(a[1]), "r"(a[2]), "r"(a[3]), "r"(b[0]), "r"(b[1]));
}

__global__ void init_rowmin_kernel() {
    int i = blockIdx.x * blockDim.x + threadIdx.x;
    if (i < NT) g_rowmin[i] = 0xFFFFFFFFFFFFFFFFULL;
}

__global__ void xnorm_kernel(const float* __restrict__ x) {
    int row = blockIdx.x * 8 + (threadIdx.x >> 5);
    int lane = threadIdx.x & 31;
    const float4* xr = (const float4*)(x + (size_t)row * DIM);
    float s = 0.f;
    #pragma unroll
    for (int i = lane; i < DIM / 4; i += 32) {
        float4 v = xr[i];
        s += v.x * v.x + v.y * v.y + v.z * v.z + v.w * v.w;
    }
    #pragma unroll
    for (int o = 16; o; o >>= 1) s += __shfl_down_sync(0xffffffffu, s, o);
    if (lane == 0) g_xnorm[row] = s;
}

__global__ void enorm_kernel(const float* __restrict__ e) {
    int j = blockIdx.x * blockDim.x + threadIdx.x;
    float s = 0.f;
    for (int d = 0; d < DIM; ++d) {
        float v = e[(size_t)d * NE + j];
        s += v * v;
    }
    g_enorm[j] = s;
}

__global__ void transpose_kernel(const float* __restrict__ e) {
    __shared__ float t[32][33];
    int j0 = blockIdx.x * 32;
    int d0 = blockIdx.y * 32;
    int tx = threadIdx.x, ty = threadIdx.y;  // 32 x 8
    #pragma unroll
    for (int r = 0; r < 32; r += 8)
        t[ty + r][tx] = e[(size_t)(d0 + ty + r) * NE + j0 + tx];
    __syncthreads();
    #pragma unroll
    for (int r = 0; r < 32; r += 8)
        g_embedT[(size_t)(j0 + ty + r) * DIM + d0 + tx] = t[tx][ty + r];
}

// ===================== 3xTF32 mma.sync GEMM + fused dist/argmin =====================
struct LdRegs { float4 a0, a1, b0, b1; };

__device__ __forceinline__ LdRegs fill_load(const float* __restrict__ X,
                                            int browg, int bcolg, int k0, int tid) {
    LdRegs l;
    int rowA = tid >> 2, c4 = tid & 3;
    l.a0 = *(const float4*)(X + (size_t)(browg + rowA) * DIM + k0 + c4 * 4);
    l.a1 = *(const float4*)(X + (size_t)(browg + rowA + 64) * DIM + k0 + c4 * 4);
    l.b0 = *(const float4*)(g_embedT + (size_t)(bcolg + rowA) * DIM + k0 + c4 * 4);
    l.b1 = *(const float4*)(g_embedT + (size_t)(bcolg + rowA + 64) * DIM + k0 + c4 * 4);
    return l;
}

__device__ __forceinline__ void split_store(float* hi_base, float* lo_base,
                                            int row, int c4, float4 v) {
    float4 hi, lo;
    hi.x = tf32_rna(v.x); lo.x = tf32_rna(v.x - hi.x);
    hi.y = tf32_rna(v.y); lo.y = tf32_rna(v.y - hi.y);
    hi.z = tf32_rna(v.z); lo.z = tf32_rna(v.z - hi.z);
    hi.w = tf32_rna(v.w); lo.w = tf32_rna(v.w - hi.w);
    *(float4*)(hi_base + row * 20 + c4 * 4) = hi;
    *(float4*)(lo_base + row * 20 + c4 * 4) = lo;
}

__device__ __forceinline__ void fill_store(float* stage, int tid, const LdRegs& l) {
    int rowA = tid >> 2, c4 = tid & 3;
    split_store(stage + A_HI, stage + A_LO, rowA,      c4, l.a0);
    split_store(stage + A_HI, stage + A_LO, rowA + 64, c4, l.a1);
    split_store(stage + B_HI, stage + B_LO, rowA,      c4, l.b0);
    split_store(stage + B_HI, stage + B_LO, rowA + 64, c4, l.b1);
}

__global__ void __launch_bounds__(256, 2) gemm_mma_kernel(const float* __restrict__ X,
                                                          float* __restrict__ distp) {
    extern __shared__ char smraw[];
    unsigned long long* smin = (unsigned long long*)(smraw + SM_SMIN_OFF);
    float* sdata = (float*)(smraw + SM_DATA_OFF);

    const int tid = threadIdx.x;
    const int wid = tid >> 5;
    const int lane = tid & 31;
    const int wm = wid & 1;          // 2 warp-rows of 64
    const int wn = wid >> 1;         // 4 warp-cols of 32
    const int browg = blockIdx.y * TILE_M;
    const int bcolg = blockIdx.x * TILE_N;
    const int lq = lane >> 2;        // 0..7
    const int lr = lane & 3;         // 0..3

    float d[4][4][4];
    #pragma unroll
    for (int mi = 0; mi < 4; mi++)
        #pragma unroll
        for (int nj = 0; nj < 4; nj++)
            #pragma unroll
            for (int c = 0; c < 4; c++) d[mi][nj][c] = 0.f;

    // prologue
    {
        LdRegs l0 = fill_load(X, browg, bcolg, 0, tid);
        fill_store(sdata, tid, l0);
    }
    __syncthreads();

    #pragma unroll 1
    for (int s = 0; s < NSTAGE; ++s) {
        LdRegs ln;
        const bool more = (s + 1 < NSTAGE);
        if (more) ln = fill_load(X, browg, bcolg, (s + 1) * KB, tid);

        const float* stg = sdata + (s & 1) * STAGE_FLOATS;
        const float* ah = stg + A_HI;
        const float* al = stg + A_LO;
        const float* bh = stg + B_HI;
        const float* bl = stg + B_LO;

        #pragma unroll
        for (int ks = 0; ks < 2; ++ks) {
            const int kc = ks * 8 + lr;
            uint32_t bhi[4][2], blo[4][2];
            #pragma unroll
            for (int nj = 0; nj < 4; nj++) {
                const int bn = wn * 32 + nj * 8 + lq;
                bhi[nj][0] = __float_as_uint(bh[bn * 20 + kc]);
                bhi[nj][1] = __float_as_uint(bh[bn * 20 + kc + 4]);
                blo[nj][0] = __float_as_uint(bl[bn * 20 + kc]);
                blo[nj][1] = __float_as_uint(bl[bn * 20 + kc + 4]);
            }
            #pragma unroll
            for (int mi = 0; mi < 4; mi++) {
                const int ar = wm * 64 + mi * 16 + lq;
                uint32_t ahi[4], alo[4];
                ahi[0] = __float_as_uint(ah[ar * 20 + kc]);
                ahi[1] = __float_as_uint(ah[(ar + 8) * 20 + kc]);
                ahi[2] = __float_as_uint(ah[ar * 20 + kc + 4]);
                ahi[3] = __float_as_uint(ah[(ar + 8) * 20 + kc + 4]);
                alo[0] = __float_as_uint(al[ar * 20 + kc]);
                alo[1] = __float_as_uint(al[(ar + 8) * 20 + kc]);
                alo[2] = __float_as_uint(al[ar * 20 + kc + 4]);
                alo[3] = __float_as_uint(al[(ar + 8) * 20 + kc + 4]);
                #pragma unroll
                for (int nj = 0; nj < 4; nj++) {
                    mma_tf32(d[mi][nj], ahi, bhi[nj]);
                    mma_tf32(d[mi][nj], ahi, blo[nj]);
                    mma_tf32(d[mi][nj], alo, bhi[nj]);
                }
            }
        }
        if (more) fill_store(sdata + ((s + 1) & 1) * STAGE_FLOATS, tid, ln);
        __syncthreads();
    }

    // ---- epilogue ----
    if (tid < 128) smin[tid] = 0xFFFFFFFFFFFFFFFFULL;
    __syncthreads();   // also fences stage buffers before reuse as dist tile

    float* sd = sdata;   // [col][132] pad -> conflict-free write & read-out
    float en8[4][2];
    #pragma unroll
    for (int nj = 0; nj < 4; nj++)
        #pragma unroll
        for (int cc = 0; cc < 2; cc++)
            en8[nj][cc] = g_enorm[bcolg + wn * 32 + nj * 8 + 2 * lr + cc];

    #pragma unroll
    for (int mi = 0; mi < 4; mi++) {
        #pragma unroll
        for (int h = 0; h < 2; h++) {
            const int row_local = wm * 64 + mi * 16 + lq + h * 8;
            const float xn = g_xnorm[browg + row_local];
            float best = 3.4e38f;
            int bcol = NE;
            #pragma unroll
            for (int nj = 0; nj < 4; nj++) {
                #pragma unroll
                for (int cc = 0; cc < 2; cc++) {
                    const int col_local = wn * 32 + nj * 8 + 2 * lr + cc;
                    const float dval = fmaf(-2.f, d[mi][nj][h * 2 + cc], xn) + en8[nj][cc];
                    sd[col_local * 132 + row_local] = dval;
                    if (dval < best) { best = dval; bcol = bcolg + col_local; }
                }
            }
            atomicMin(&smin[row_local],
                      ((unsigned long long)__float_as_uint(best) << 32) | (unsigned)bcol);
        }
    }
    __syncthreads();

    if (tid < 128) atomicMin(&g_rowmin[browg + tid], smin[tid]);

    if (distp) {
        float* dbase = distp + (size_t)browg * NE + bcolg;
        #pragma unroll 4
        for (int j = 0; j < TILE_M * TILE_N / 256; ++j) {
            const int i2 = tid + j * 256;
            const int r = i2 >> 7, c = i2 & 127;
            dbase[(size_t)r * NE + c] = sd[c * 132 + r];
        }
    }
}

// gather quantize rows, ST output, per-row loss
__global__ void gather_kernel(const float* __restrict__ X,
                              float* __restrict__ qp, float* __restrict__ indp) {
    const int row = blockIdx.x;
    const int tid = threadIdx.x;   // 128 threads
    const unsigned long long pk = g_rowmin[row];
    const unsigned ind = (unsigned)(pk & 0xFFFFFFFFu);
    if (indp && tid == 0) indp[row] = (float)ind;

    const float4 q = ((const float4*)(g_embedT + (size_t)ind * DIM))[tid];
    const float4 x = ((const float4*)(X + (size_t)row * DIM))[tid];

    if (qp) {
        float4 o;
        o.x = x.x + (q.x - x.x); o.y = x.y + (q.y - x.y);
        o.z = x.z + (q.z - x.z); o.w = x.w + (q.w - x.w);
        ((float4*)(qp + (size_t)row * DIM))[tid] = o;
    }
    float dx = x.x - q.x, dy = x.y - q.y, dz = x.z - q.z, dw = x.w - q.w;
    float ls = dx * dx + dy * dy + dz * dz + dw * dw;
    __shared__ float red[128];
    red[tid] = ls;
    __syncthreads();
    #pragma unroll
    for (int s = 64; s; s >>= 1) {
        if (tid < s) red[tid] += red[tid + s];
        __syncthreads();
    }
    if (tid == 0) g_rowloss[row] = red[0];
}

__global__ void loss_kernel(float* __restrict__ lossp) {
    __shared__ float red[512];
    const int tid = threadIdx.x;
    float s = 0.f;
    for (int i = tid; i < NT; i += 512) s += g_rowloss[i];
    red[tid] = s;
    __syncthreads();
    #pragma unroll
    for (int st = 256; st; st >>= 1) {
        if (tid < st) red[tid] += red[tid + st];
        __syncthreads();
    }
    if (tid == 0) *lossp = red[0] * (1.0f / ((float)NT * (float)DIM));
}

extern "C" void kernel_launch(void* const* d_in, const int* in_sizes, int n_in,
                              void* d_out, int out_size) {
    const float* X = (const float*)d_in[0];   // [NT, DIM]
    const float* E = (const float*)d_in[1];   // [DIM, NE]
    float* out = (float*)d_out;

    const long long QN = (long long)NT * DIM;
    const long long DN = (long long)NT * NE;
    const long long OS = (long long)out_size;

    float *qp = 0, *indp = 0, *lossp = 0, *distp = 0;
    if (OS == QN + NT + 1 + DN) {
        qp = out; indp = out + QN; lossp = out + QN + NT; distp = out + QN + NT + 1;
    } else if (OS == QN) { qp = out;
    } else if (OS == DN) { distp = out;
    } else if (OS == NT) { indp = out;
    } else if (OS == 1)  { lossp = out;
    } else if (OS == QN + NT + 1) { qp = out; indp = out + QN; lossp = out + QN + NT;
    } else {
        if (OS >= QN) qp = out;
        if (OS >= QN + NT) indp = out + QN;
        if (OS >= QN + NT + 1) lossp = out + QN + NT;
        if (OS >= QN + NT + 1 + DN) distp = out + QN + NT + 1;
    }

    cudaFuncSetAttribute(gemm_mma_kernel, cudaFuncAttributeMaxDynamicSharedMemorySize, SMEM_TOTAL);

    init_rowmin_kernel<<<NT / 256, 256>>>();
    xnorm_kernel<<<NT / 8, 256>>>(X);
    enorm_kernel<<<NE / 256, 256>>>(E);
    transpose_kernel<<<dim3(NE / 32, DIM / 32), dim3(32, 8)>>>(E);
    gemm_mma_kernel<<<dim3(NE / TILE_N, NT / TILE_M), 256, SMEM_TOTAL>>>(X, distp);
    gather_kernel<<<NT, 128>>>(X, qp, indp);
    if (lossp) loss_kernel<<<1, 512>>>(lossp);
}

// round 5
// speedup vs baseline: 1.8503x; 1.2534x over previous
#include <cuda_runtime.h>
#include <stdint.h>

#define NT 32768
#define DIM 512
#define NE 8192

#define TILE_M 128
#define TILE_N 128
#define KB 16
#define NKB (DIM / KB)        // 32 k16 blocks
#define NBY (NT / TILE_M)     // 256
#define NBX (NE / TILE_N)     // 64

// smem: [0,1024) smin; [1024, +3*32768) cp.async stages (A 16KB + B 16KB each)
#define SM_SMIN_OFF 0
#define SM_DATA_OFF 1024
#define STAGE_BYTES 32768
#define SMEM_TOTAL (1024 + 3 * STAGE_BYTES)

// ---- device scratch ----
__device__ unsigned long long g_rowmin[NT];
__device__ float g_xnorm[NT];
__device__ float g_enorm[NE];
__device__ float g_embedT[(size_t)NE * DIM];              // 16 MB (gather)
__device__ float g_rowloss[NT];
__device__ float4 XA[(size_t)NBY * NKB * 1024];           // 134 MB frag-ordered hi/lo
__device__ float4 EB[(size_t)NBX * NKB * 1024];           // 33.5 MB frag-ordered

__device__ __forceinline__ float tf32_rna(float x) {
    uint32_t r;
    asm("cvt.rna.tf32.f32 %0, %1;" : "=r"(r) : "f"(x));
    return __uint_as_float(r);
}
__device__ __forceinline__ void mma_tf32(float* d, const uint32_t* a, const uint32_t* b) {
    asm volatile("mma.sync.aligned.m16n8k8.row.col.f32.tf32.tf32.f32 "
                 "{%0,%1,%2,%3}, {%4,%5,%6,%7}, {%8,%9}, {%0,%1,%2,%3};"
                 : "+f"(d[0]), "+f"(d[1]), "+f"(d[2]), "+f"(d[3])
                 : "r"(a[0]), "r"(a[1]), "r"(a[2]), "r"(a[3]), "r"(b[0]), "r"(b[1]));
}
__device__ __forceinline__ uint32_t smem_u32(const void* p) {
    uint32_t a;
    asm("{ .reg .u64 t; cvta.to.shared.u64 t, %1; cvt.u32.u64 %0, t; }" : "=r"(a) : "l"(p));
    return a;
}
#define CP_ASYNC16(sa, g) asm volatile("cp.async.cg.shared.global [%0], [%1], 16;" :: "r"(sa), "l"(g))
#define CP_COMMIT()       asm volatile("cp.async.commit_group;")
#define CP_WAIT2()        asm volatile("cp.async.wait_group 2;")
#define CP_WAIT0()        asm volatile("cp.async.wait_group 0;")

// ---- launch 1: split X -> fragment-ordered XA ----
__global__ void prep_x_kernel(const float* __restrict__ X) {
    const int by = blockIdx.x >> 5, kb = blockIdx.x & 31;
    const int u = threadIdx.x >> 5, lane = threadIdx.x & 31;
    const int lq = lane >> 2, lr = lane & 3;
    #pragma unroll
    for (int h = 0; h < 2; h++) {
        const int unit = u + h * 8;                     // ((wm*4+mi)*2+ks)
        const int wm = unit >> 3, mi = (unit >> 1) & 3, ks = unit & 1;
        const int r0 = by * 128 + wm * 64 + mi * 16 + lq;
        const int k0 = kb * 16 + ks * 8 + lr;
        const float v0 = X[(size_t)r0 * DIM + k0];
        const float v1 = X[(size_t)(r0 + 8) * DIM + k0];
        const float v2 = X[(size_t)r0 * DIM + k0 + 4];
        const float v3 = X[(size_t)(r0 + 8) * DIM + k0 + 4];
        float4 hi, lo;
        hi.x = tf32_rna(v0); lo.x = tf32_rna(v0 - hi.x);
        hi.y = tf32_rna(v1); lo.y = tf32_rna(v1 - hi.y);
        hi.z = tf32_rna(v2); lo.z = tf32_rna(v2 - hi.z);
        hi.w = tf32_rna(v3); lo.w = tf32_rna(v3 - hi.w);
        const size_t base = ((size_t)by * NKB + kb) * 1024 + unit * 64;
        XA[base + lane] = hi;
        XA[base + 32 + lane] = lo;
    }
}

// ---- launch 2: split E -> fragment-ordered EB ----
__global__ void prep_e_kernel(const float* __restrict__ E) {
    const int bx = blockIdx.x >> 5, kb = blockIdx.x & 31;
    const int u = threadIdx.x >> 5, lane = threadIdx.x & 31;
    const int lq = lane >> 2, lr = lane & 3;
    #pragma unroll
    for (int h = 0; h < 4; h++) {
        const int unit = u + h * 8;                     // ((wn*4+nj)*2+ks), 32 units
        const int wn = unit >> 3, nj = (unit >> 1) & 3, ks = unit & 1;
        const int c = bx * 128 + wn * 32 + nj * 8 + lq;
        const int k = kb * 16 + ks * 8 + lr;
        const float v0 = E[(size_t)k * NE + c];
        const float v1 = E[(size_t)(k + 4) * NE + c];
        float4 p;
        p.x = tf32_rna(v0); p.z = tf32_rna(v0 - p.x);
        p.y = tf32_rna(v1); p.w = tf32_rna(v1 - p.y);
        EB[((size_t)bx * NKB + kb) * 1024 + unit * 32 + lane] = p;
    }
}

// ---- launch 3: transpose + init rowmin + xnorm + enorm (fused by block range) ----
__global__ void misc_prep_kernel(const float* __restrict__ X, const float* __restrict__ E) {
    const int b = blockIdx.x;
    const int tid = threadIdx.x;
    if (b < 4096) {                                     // transpose E -> g_embedT
        __shared__ float t[32][33];
        const int j0 = (b & 255) * 32, d0 = (b >> 8) * 32;
        const int tx = tid & 31, ty = tid >> 5;
        #pragma unroll
        for (int r = 0; r < 32; r += 8)
            t[ty + r][tx] = E[(size_t)(d0 + ty + r) * NE + j0 + tx];
        __syncthreads();
        #pragma unroll
        for (int r = 0; r < 32; r += 8)
            g_embedT[(size_t)(j0 + ty + r) * DIM + d0 + tx] = t[tx][ty + r];
    } else if (b < 4224) {                              // init rowmin
        g_rowmin[(b - 4096) * 256 + tid] = 0xFFFFFFFFFFFFFFFFULL;
    } else if (b < 8320) {                              // xnorm, one warp per row
        const int row = (b - 4224) * 8 + (tid >> 5);
        const int lane = tid & 31;
        const float4* xr = (const float4*)(X + (size_t)row * DIM);
        float s = 0.f;
        #pragma unroll
        for (int i = lane; i < DIM / 4; i += 32) {
            float4 v = xr[i];
            s += v.x * v.x + v.y * v.y + v.z * v.z + v.w * v.w;
        }
        #pragma unroll
        for (int o = 16; o; o >>= 1) s += __shfl_down_sync(0xffffffffu, s, o);
        if (lane == 0) g_xnorm[row] = s;
    } else {                                            // enorm
        const int j = (b - 8320) * 256 + tid;
        float s = 0.f;
        for (int d = 0; d < DIM; ++d) {
            float v = E[(size_t)d * NE + j];
            s += v * v;
        }
        g_enorm[j] = s;
    }
}

// ---- launch 4: 3xTF32 mma.sync GEMM, cp.async 3-stage, fused dist/argmin ----
__device__ __forceinline__ void issue_stage(uint32_t sm_stage, const float4* ga,
                                            const float4* gb, int tid) {
    #pragma unroll
    for (int c = 0; c < 4; c++) {
        CP_ASYNC16(sm_stage + (tid + c * 256) * 16, ga + tid + c * 256);
        CP_ASYNC16(sm_stage + 16384 + (tid + c * 256) * 16, gb + tid + c * 256);
    }
    CP_COMMIT();
}

__global__ void __launch_bounds__(256, 2) gemm_mma_kernel(float* __restrict__ distp) {
    extern __shared__ char smraw[];
    unsigned long long* smin = (unsigned long long*)(smraw + SM_SMIN_OFF);
    float* sdata = (float*)(smraw + SM_DATA_OFF);
    const uint32_t smb = smem_u32(smraw) + SM_DATA_OFF;

    const int tid = threadIdx.x;
    const int wid = tid >> 5;
    const int lane = tid & 31;
    const int wm = wid & 1;
    const int wn = wid >> 1;
    const int browg = blockIdx.y * TILE_M;
    const int bcolg = blockIdx.x * TILE_N;
    const int lq = lane >> 2;
    const int lr = lane & 3;

    const float4* ga = XA + (size_t)blockIdx.y * NKB * 1024;
    const float4* gb = EB + (size_t)blockIdx.x * NKB * 1024;

    float d[4][4][4];
    #pragma unroll
    for (int mi = 0; mi < 4; mi++)
        #pragma unroll
        for (int nj = 0; nj < 4; nj++)
            #pragma unroll
            for (int c = 0; c < 4; c++) d[mi][nj][c] = 0.f;

    issue_stage(smb, ga, gb, tid);
    issue_stage(smb + STAGE_BYTES, ga + 1024, gb + 1024, tid);

    // per-warp fragment smem byte offsets (within a stage)
    const uint32_t aoff0 = (uint32_t)(((wm * 4) * 2) * 1024 + lane * 16);  // mi=0,ks=0
    const uint32_t boff0 = (uint32_t)(16384 + ((wn * 4) * 2) * 512 + lane * 16);

    #pragma unroll 1
    for (int i = 0; i < NKB; ++i) {
        if (i + 2 < NKB)
            issue_stage(smb + ((i + 2) % 3) * STAGE_BYTES,
                        ga + (size_t)(i + 2) * 1024, gb + (size_t)(i + 2) * 1024, tid);
        CP_WAIT2();
        __syncthreads();

        const char* stg = (const char*)sdata + (i % 3) * STAGE_BYTES;
        #pragma unroll
        for (int ks = 0; ks < 2; ++ks) {
            uint32_t bh[4][2], bl[4][2];
            #pragma unroll
            for (int nj = 0; nj < 4; nj++) {
                const float4 p = *(const float4*)(stg + boff0 + (nj * 2 + ks) * 512);
                bh[nj][0] = __float_as_uint(p.x); bh[nj][1] = __float_as_uint(p.y);
                bl[nj][0] = __float_as_uint(p.z); bl[nj][1] = __float_as_uint(p.w);
            }
            #pragma unroll
            for (int mi = 0; mi < 4; mi++) {
                const char* au = stg + aoff0 + (mi * 2 + ks) * 1024;
                const float4 h4 = *(const float4*)au;
                const float4 l4 = *(const float4*)(au + 512);
                uint32_t ah[4] = {__float_as_uint(h4.x), __float_as_uint(h4.y),
                                  __float_as_uint(h4.z), __float_as_uint(h4.w)};
                uint32_t al[4] = {__float_as_uint(l4.x), __float_as_uint(l4.y),
                                  __float_as_uint(l4.z), __float_as_uint(l4.w)};
                #pragma unroll
                for (int nj = 0; nj < 4; nj++) {
                    mma_tf32(d[mi][nj], ah, bh[nj]);
                    mma_tf32(d[mi][nj], ah, bl[nj]);
                    mma_tf32(d[mi][nj], al, bh[nj]);
                }
            }
        }
        __syncthreads();
    }
    CP_WAIT0();

    // ---- epilogue (identical math to passing R4) ----
    if (tid < 128) smin[tid] = 0xFFFFFFFFFFFFFFFFULL;
    __syncthreads();

    float* sd = sdata;   // [col][132] pad
    float en8[4][2];
    #pragma unroll
    for (int nj = 0; nj < 4; nj++)
        #pragma unroll
        for (int cc = 0; cc < 2; cc++)
            en8[nj][cc] = g_enorm[bcolg + wn * 32 + nj * 8 + 2 * lr + cc];

    #pragma unroll
    for (int mi = 0; mi < 4; mi++) {
        #pragma unroll
        for (int h = 0; h < 2; h++) {
            const int row_local = wm * 64 + mi * 16 + lq + h * 8;
            const float xn = g_xnorm[browg + row_local];
            float best = 3.4e38f;
            int bcol = NE;
            #pragma unroll
            for (int nj = 0; nj < 4; nj++) {
                #pragma unroll
                for (int cc = 0; cc < 2; cc++) {
                    const int col_local = wn * 32 + nj * 8 + 2 * lr + cc;
                    const float dval = fmaf(-2.f, d[mi][nj][h * 2 + cc], xn) + en8[nj][cc];
                    sd[col_local * 132 + row_local] = dval;
                    if (dval < best) { best = dval; bcol = bcolg + col_local; }
                }
            }
            atomicMin(&smin[row_local],
                      ((unsigned long long)__float_as_uint(best) << 32) | (unsigned)bcol);
        }
    }
    __syncthreads();

    if (tid < 128) atomicMin(&g_rowmin[browg + tid], smin[tid]);

    if (distp) {
        float* dbase = distp + (size_t)browg * NE + bcolg;
        #pragma unroll 4
        for (int j = 0; j < TILE_M * TILE_N / 256; ++j) {
            const int i2 = tid + j * 256;
            const int r = i2 >> 7, c = i2 & 127;
            dbase[(size_t)r * NE + c] = sd[c * 132 + r];
        }
    }
}

// ---- launch 5: gather quantize rows, ind, per-row loss ----
__global__ void gather_kernel(const float* __restrict__ X,
                              float* __restrict__ qp, float* __restrict__ indp) {
    const int row = blockIdx.x;
    const int tid = threadIdx.x;   // 128
    const unsigned long long pk = g_rowmin[row];
    const unsigned ind = (unsigned)(pk & 0xFFFFFFFFu);
    if (indp && tid == 0) indp[row] = (float)ind;

    const float4 q = ((const float4*)(g_embedT + (size_t)ind * DIM))[tid];
    const float4 x = ((const float4*)(X + (size_t)row * DIM))[tid];

    if (qp) {
        float4 o;
        o.x = x.x + (q.x - x.x); o.y = x.y + (q.y - x.y);
        o.z = x.z + (q.z - x.z); o.w = x.w + (q.w - x.w);
        ((float4*)(qp + (size_t)row * DIM))[tid] = o;
    }
    float dx = x.x - q.x, dy = x.y - q.y, dz = x.z - q.z, dw = x.w - q.w;
    float ls = dx * dx + dy * dy + dz * dz + dw * dw;
    __shared__ float red[128];
    red[tid] = ls;
    __syncthreads();
    #pragma unroll
    for (int s = 64; s; s >>= 1) {
        if (tid < s) red[tid] += red[tid + s];
        __syncthreads();
    }
    if (tid == 0) g_rowloss[row] = red[0];
}

__global__ void loss_kernel(float* __restrict__ lossp) {
    __shared__ float red[512];
    const int tid = threadIdx.x;
    float s = 0.f;
    for (int i = tid; i < NT; i += 512) s += g_rowloss[i];
    red[tid] = s;
    __syncthreads();
    #pragma unroll
    for (int st = 256; st; st >>= 1) {
        if (tid < st) red[tid] += red[tid + st];
        __syncthreads();
    }
    if (tid == 0) *lossp = red[0] * (1.0f / ((float)NT * (float)DIM));
}

extern "C" void kernel_launch(void* const* d_in, const int* in_sizes, int n_in,
                              void* d_out, int out_size) {
    const float* X = (const float*)d_in[0];
    const float* E = (const float*)d_in[1];
    float* out = (float*)d_out;

    const long long QN = (long long)NT * DIM;
    const long long DN = (long long)NT * NE;
    const long long OS = (long long)out_size;

    float *qp = 0, *indp = 0, *lossp = 0, *distp = 0;
    if (OS == QN + NT + 1 + DN) {
        qp = out; indp = out + QN; lossp = out + QN + NT; distp = out + QN + NT + 1;
    } else if (OS == QN) { qp = out;
    } else if (OS == DN) { distp = out;
    } else if (OS == NT) { indp = out;
    } else if (OS == 1)  { lossp = out;
    } else if (OS == QN + NT + 1) { qp = out; indp = out + QN; lossp = out + QN + NT;
    } else {
        if (OS >= QN) qp = out;
        if (OS >= QN + NT) indp = out + QN;
        if (OS >= QN + NT + 1) lossp = out + QN + NT;
        if (OS >= QN + NT + 1 + DN) distp = out + QN + NT + 1;
    }

    cudaFuncSetAttribute(gemm_mma_kernel, cudaFuncAttributeMaxDynamicSharedMemorySize, SMEM_TOTAL);

    prep_x_kernel<<<NBY * NKB, 256>>>(X);                       // 1
    prep_e_kernel<<<NBX * NKB, 256>>>(E);                       // 2
    misc_prep_kernel<<<8352, 256>>>(X, E);                      // 3
    gemm_mma_kernel<<<dim3(NBX, NBY), 256, SMEM_TOTAL>>>(distp);// 4 (ncu slot)
    gather_kernel<<<NT, 128>>>(X, qp, indp);                    // 5
    if (lossp) loss_kernel<<<1, 512>>>(lossp);                  // 6
}

// round 6
// speedup vs baseline: 3.5881x; 1.9392x over previous
#include <cuda_runtime.h>
#include <stdint.h>

#define NT 32768
#define DIM 512
#define NE 8192

#define TILE_M 128
#define TILE_N 128
#define KB 16
#define NKB (DIM / KB)        // 32
#define NBY (NT / TILE_M)     // 256
#define NBX (NE / TILE_N)     // 64

// smem: [0,1024) smin; [1024, ...) cp.async stages (A 8KB + B 8KB each) / dist tile
#define SM_SMIN_OFF 0
#define SM_DATA_OFF 1024
#define STAGE_BYTES 16384
#define SMEM_TOTAL (1024 + 128 * 132 * 4)   // 68608; stages (49152) fit inside

// ---- device scratch ----
__device__ unsigned long long g_rowmin[NT];
__device__ float g_xnorm[NT];
__device__ float g_enorm[NE];
__device__ float g_embedT[(size_t)NE * DIM];              // 16 MB (gather/rescore)
__device__ float g_rowloss[NT];
__device__ float4 XA[(size_t)NBY * NKB * 512];            // 67 MB hi-only frag-ordered
__device__ float4 EB[(size_t)NBX * NKB * 512];            // 16.8 MB hi-only frag-ordered

__device__ __forceinline__ float tf32_rna(float x) {
    uint32_t r;
    asm("cvt.rna.tf32.f32 %0, %1;" : "=r"(r) : "f"(x));
    return __uint_as_float(r);
}
__device__ __forceinline__ void mma_tf32(float* d, const uint32_t* a, const uint32_t* b) {
    asm volatile("mma.sync.aligned.m16n8k8.row.col.f32.tf32.tf32.f32 "
                 "{%0,%1,%2,%3}, {%4,%5,%6,%7}, {%8,%9}, {%0,%1,%2,%3};"
                 : "+f"(d[0]), "+f"(d[1]), "+f"(d[2]), "+f"(d[3])
                 : "r"(a[0]), "r"(a[1]), "r"(a[2]), "r"(a[3]), "r"(b[0]), "r"(b[1]));
}
__device__ __forceinline__ uint32_t smem_u32(const void* p) {
    uint32_t a;
    asm("{ .reg .u64 t; cvta.to.shared.u64 t, %1; cvt.u32.u64 %0, t; }" : "=r"(a) : "l"(p));
    return a;
}
#define CP_ASYNC16(sa, g) asm volatile("cp.async.cg.shared.global [%0], [%1], 16;" :: "r"(sa), "l"(g))
#define CP_COMMIT()       asm volatile("cp.async.commit_group;")
#define CP_WAIT2()        asm volatile("cp.async.wait_group 2;")
#define CP_WAIT0()        asm volatile("cp.async.wait_group 0;")

// ---- launch 1: X -> hi-only fragment-ordered XA ----
// unit = wm*8 + mi*2 + ks ; float4 = (a0,a1,a2,a3) for m16n8k8 row-major A
__global__ void prep_x_kernel(const float* __restrict__ X) {
    const int by = blockIdx.x >> 5, kb = blockIdx.x & 31;
    const int u = threadIdx.x >> 5, lane = threadIdx.x & 31;
    const int lq = lane >> 2, lr = lane & 3;
    #pragma unroll
    for (int h = 0; h < 2; h++) {
        const int unit = u + h * 8;
        const int wm = unit >> 3, mi = (unit >> 1) & 3, ks = unit & 1;
        const int r0 = by * 128 + wm * 64 + mi * 16 + lq;
        const int k0 = kb * 16 + ks * 8 + lr;
        float4 hi;
        hi.x = tf32_rna(X[(size_t)r0 * DIM + k0]);
        hi.y = tf32_rna(X[(size_t)(r0 + 8) * DIM + k0]);
        hi.z = tf32_rna(X[(size_t)r0 * DIM + k0 + 4]);
        hi.w = tf32_rna(X[(size_t)(r0 + 8) * DIM + k0 + 4]);
        XA[((size_t)by * NKB + kb) * 512 + unit * 32 + lane] = hi;
    }
}

// ---- launch 2: E -> hi-only fragment-ordered EB ----
// unit2 = wn*4 + ks*2 + njp ; float4 = (b0,b1 of nj=2*njp, b0,b1 of nj=2*njp+1)
__global__ void prep_e_kernel(const float* __restrict__ E) {
    const int bx = blockIdx.x >> 5, kb = blockIdx.x & 31;
    const int u = threadIdx.x >> 5, lane = threadIdx.x & 31;
    const int lq = lane >> 2, lr = lane & 3;
    #pragma unroll
    for (int h = 0; h < 2; h++) {
        const int unit = u + h * 8;
        const int wn = unit >> 2, ks = (unit >> 1) & 1, njp = unit & 1;
        const int c0 = bx * 128 + wn * 32 + (2 * njp) * 8 + lq;
        const int k = kb * 16 + ks * 8 + lr;
        float4 p;
        p.x = tf32_rna(E[(size_t)k * NE + c0]);
        p.y = tf32_rna(E[(size_t)(k + 4) * NE + c0]);
        p.z = tf32_rna(E[(size_t)k * NE + c0 + 8]);
        p.w = tf32_rna(E[(size_t)(k + 4) * NE + c0 + 8]);
        EB[((size_t)bx * NKB + kb) * 512 + unit * 32 + lane] = p;
    }
}

// ---- launch 3: transpose + init rowmin + xnorm + enorm ----
__global__ void misc_prep_kernel(const float* __restrict__ X, const float* __restrict__ E) {
    const int b = blockIdx.x;
    const int tid = threadIdx.x;
    if (b < 4096) {
        __shared__ float t[32][33];
        const int j0 = (b & 255) * 32, d0 = (b >> 8) * 32;
        const int tx = tid & 31, ty = tid >> 5;
        #pragma unroll
        for (int r = 0; r < 32; r += 8)
            t[ty + r][tx] = E[(size_t)(d0 + ty + r) * NE + j0 + tx];
        __syncthreads();
        #pragma unroll
        for (int r = 0; r < 32; r += 8)
            g_embedT[(size_t)(j0 + ty + r) * DIM + d0 + tx] = t[tx][ty + r];
    } else if (b < 4224) {
        g_rowmin[(b - 4096) * 256 + tid] = 0xFFFFFFFFFFFFFFFFULL;
    } else if (b < 8320) {
        const int row = (b - 4224) * 8 + (tid >> 5);
        const int lane = tid & 31;
        const float4* xr = (const float4*)(X + (size_t)row * DIM);
        float s = 0.f;
        #pragma unroll
        for (int i = lane; i < DIM / 4; i += 32) {
            float4 v = xr[i];
            s += v.x * v.x + v.y * v.y + v.z * v.z + v.w * v.w;
        }
        #pragma unroll
        for (int o = 16; o; o >>= 1) s += __shfl_down_sync(0xffffffffu, s, o);
        if (lane == 0) g_xnorm[row] = s;
    } else {
        const int j = (b - 8320) * 256 + tid;
        float s = 0.f;
        for (int d = 0; d < DIM; ++d) {
            float v = E[(size_t)d * NE + j];
            s += v * v;
        }
        g_enorm[j] = s;
    }
}

// ---- launch 4: pure-TF32 mma.sync GEMM, cp.async 3-stage, fused dist + tf32 argmin ----
__device__ __forceinline__ void issue_stage(uint32_t sm_stage, const float4* ga,
                                            const float4* gb, int tid) {
    CP_ASYNC16(sm_stage + tid * 16, ga + tid);
    CP_ASYNC16(sm_stage + (tid + 256) * 16, ga + tid + 256);
    CP_ASYNC16(sm_stage + 8192 + tid * 16, gb + tid);
    CP_ASYNC16(sm_stage + 8192 + (tid + 256) * 16, gb + tid + 256);
    CP_COMMIT();
}

__global__ void __launch_bounds__(256, 2) gemm_mma_kernel(float* __restrict__ distp) {
    extern __shared__ char smraw[];
    unsigned long long* smin = (unsigned long long*)(smraw + SM_SMIN_OFF);
    float* sdata = (float*)(smraw + SM_DATA_OFF);
    const uint32_t smb = smem_u32(smraw) + SM_DATA_OFF;

    const int tid = threadIdx.x;
    const int wid = tid >> 5;
    const int lane = tid & 31;
    const int wm = wid & 1;
    const int wn = wid >> 1;
    const int browg = blockIdx.y * TILE_M;
    const int bcolg = blockIdx.x * TILE_N;
    const int lq = lane >> 2;
    const int lr = lane & 3;

    const float4* ga = XA + (size_t)blockIdx.y * NKB * 512;
    const float4* gb = EB + (size_t)blockIdx.x * NKB * 512;

    float d[4][4][4];
    #pragma unroll
    for (int mi = 0; mi < 4; mi++)
        #pragma unroll
        for (int nj = 0; nj < 4; nj++)
            #pragma unroll
            for (int c = 0; c < 4; c++) d[mi][nj][c] = 0.f;

    issue_stage(smb, ga, gb, tid);
    issue_stage(smb + STAGE_BYTES, ga + 512, gb + 512, tid);

    const uint32_t abase = (uint32_t)(wm * 8 * 32 + lane) * 16;          // + (mi*2+ks)*512
    const uint32_t bbase = 8192u + (uint32_t)(wn * 4 * 32 + lane) * 16;  // + (ks*2+njp)*512

    #pragma unroll 1
    for (int i = 0; i < NKB; ++i) {
        if (i + 2 < NKB)
            issue_stage(smb + ((i + 2) % 3) * STAGE_BYTES,
                        ga + (size_t)(i + 2) * 512, gb + (size_t)(i + 2) * 512, tid);
        CP_WAIT2();
        __syncthreads();

        const char* stg = (const char*)sdata + (i % 3) * STAGE_BYTES;
        #pragma unroll
        for (int ks = 0; ks < 2; ++ks) {
            uint32_t bh[4][2];
            #pragma unroll
            for (int njp = 0; njp < 2; njp++) {
                const float4 p = *(const float4*)(stg + bbase + (ks * 2 + njp) * 512);
                bh[2 * njp][0] = __float_as_uint(p.x);
                bh[2 * njp][1] = __float_as_uint(p.y);
                bh[2 * njp + 1][0] = __float_as_uint(p.z);
                bh[2 * njp + 1][1] = __float_as_uint(p.w);
            }
            #pragma unroll
            for (int mi = 0; mi < 4; mi++) {
                const float4 a4 = *(const float4*)(stg + abase + (mi * 2 + ks) * 512);
                uint32_t ah[4] = {__float_as_uint(a4.x), __float_as_uint(a4.y),
                                  __float_as_uint(a4.z), __float_as_uint(a4.w)};
                #pragma unroll
                for (int nj = 0; nj < 4; nj++)
                    mma_tf32(d[mi][nj], ah, bh[nj]);
            }
        }
        __syncthreads();
    }
    CP_WAIT0();

    // ---- epilogue: dist + per-row tf32 argmin ----
    if (tid < 128) smin[tid] = 0xFFFFFFFFFFFFFFFFULL;
    __syncthreads();

    float* sd = sdata;   // [col][132] pad
    float en8[4][2];
    #pragma unroll
    for (int nj = 0; nj < 4; nj++)
        #pragma unroll
        for (int cc = 0; cc < 2; cc++)
            en8[nj][cc] = g_enorm[bcolg + wn * 32 + nj * 8 + 2 * lr + cc];

    #pragma unroll
    for (int mi = 0; mi < 4; mi++) {
        #pragma unroll
        for (int h = 0; h < 2; h++) {
            const int row_local = wm * 64 + mi * 16 + lq + h * 8;
            const float xn = g_xnorm[browg + row_local];
            float best = 3.4e38f;
            int bcol = NE;
            #pragma unroll
            for (int nj = 0; nj < 4; nj++) {
                #pragma unroll
                for (int cc = 0; cc < 2; cc++) {
                    const int col_local = wn * 32 + nj * 8 + 2 * lr + cc;
                    const float dval = fmaf(-2.f, d[mi][nj][h * 2 + cc], xn) + en8[nj][cc];
                    sd[col_local * 132 + row_local] = dval;
                    if (dval < best) { best = dval; bcol = bcolg + col_local; }
                }
            }
            atomicMin(&smin[row_local],
                      ((unsigned long long)__float_as_uint(best) << 32) | (unsigned)bcol);
        }
    }
    __syncthreads();

    if (tid < 128) atomicMin(&g_rowmin[browg + tid], smin[tid]);

    if (distp) {
        float* dbase = distp + (size_t)browg * NE + bcolg;
        #pragma unroll 4
        for (int j = 0; j < TILE_M * TILE_N / 256; ++j) {
            const int i2 = tid + j * 256;
            const int r = i2 >> 7, c = i2 & 127;
            dbase[(size_t)r * NE + c] = sd[c * 132 + r];
        }
    }
}

// ---- launch 5: margin-candidate scan + exact fp32 rescore of the argmin ----
__global__ void scan_rescore_kernel(const float* __restrict__ X,
                                    const float* __restrict__ distp) {
    const int row = blockIdx.x;
    const int tid = threadIdx.x;   // 256
    __shared__ int scount;
    __shared__ int cand[16];
    __shared__ float red[256];
    __shared__ unsigned long long sbest;
    if (tid == 0) { scount = 0; sbest = 0xFFFFFFFFFFFFFFFFULL; }
    __syncthreads();

    const float minv = __uint_as_float((unsigned)(g_rowmin[row] >> 32));
    const float thr = minv + 1.0f;     // >> 20 sigma of tf32 dist error
    const float* dr = distp + (size_t)row * NE;
    for (int i = tid; i < NE; i += 256) {
        const float v = dr[i];
        if (v <= thr) {
            const int s = atomicAdd(&scount, 1);
            if (s < 16) cand[s] = i;
        }
    }
    __syncthreads();
    const int n = scount < 16 ? scount : 16;

    const float xn = g_xnorm[row];
    const float2 xv = ((const float2*)(X + (size_t)row * DIM))[tid];
    for (int c = 0; c < n; ++c) {
        const int col = cand[c];
        const float2 ev = ((const float2*)(g_embedT + (size_t)col * DIM))[tid];
        red[tid] = xv.x * ev.x + xv.y * ev.y;
        __syncthreads();
        #pragma unroll
        for (int s = 128; s; s >>= 1) {
            if (tid < s) red[tid] += red[tid + s];
            __syncthreads();
        }
        if (tid == 0) {
            const float dv = fmaf(-2.f, red[0], xn) + g_enorm[col];
            const unsigned long long pk =
                ((unsigned long long)__float_as_uint(dv) << 32) | (unsigned)col;
            if (pk < sbest) sbest = pk;
        }
        __syncthreads();
    }
    if (tid == 0) g_rowmin[row] = sbest;
}

// ---- launch 6: gather quantize rows, ind, per-row loss ----
__global__ void gather_kernel(const float* __restrict__ X,
                              float* __restrict__ qp, float* __restrict__ indp) {
    const int row = blockIdx.x;
    const int tid = threadIdx.x;   // 128
    const unsigned long long pk = g_rowmin[row];
    const unsigned ind = (unsigned)(pk & 0xFFFFFFFFu);
    if (indp && tid == 0) indp[row] = (float)ind;

    const float4 q = ((const float4*)(g_embedT + (size_t)ind * DIM))[tid];
    const float4 x = ((const float4*)(X + (size_t)row * DIM))[tid];

    if (qp) {
        float4 o;
        o.x = x.x + (q.x - x.x); o.y = x.y + (q.y - x.y);
        o.z = x.z + (q.z - x.z); o.w = x.w + (q.w - x.w);
        ((float4*)(qp + (size_t)row * DIM))[tid] = o;
    }
    float dx = x.x - q.x, dy = x.y - q.y, dz = x.z - q.z, dw = x.w - q.w;
    float ls = dx * dx + dy * dy + dz * dz + dw * dw;
    __shared__ float red[128];
    red[tid] = ls;
    __syncthreads();
    #pragma unroll
    for (int s = 64; s; s >>= 1) {
        if (tid < s) red[tid] += red[tid + s];
        __syncthreads();
    }
    if (tid == 0) g_rowloss[row] = red[0];
}

__global__ void loss_kernel(float* __restrict__ lossp) {
    __shared__ float red[512];
    const int tid = threadIdx.x;
    float s = 0.f;
    for (int i = tid; i < NT; i += 512) s += g_rowloss[i];
    red[tid] = s;
    __syncthreads();
    #pragma unroll
    for (int st = 256; st; st >>= 1) {
        if (tid < st) red[tid] += red[tid + st];
        __syncthreads();
    }
    if (tid == 0) *lossp = red[0] * (1.0f / ((float)NT * (float)DIM));
}

extern "C" void kernel_launch(void* const* d_in, const int* in_sizes, int n_in,
                              void* d_out, int out_size) {
    const float* X = (const float*)d_in[0];
    const float* E = (const float*)d_in[1];
    float* out = (float*)d_out;

    const long long QN = (long long)NT * DIM;
    const long long DN = (long long)NT * NE;
    const long long OS = (long long)out_size;

    float *qp = 0, *indp = 0, *lossp = 0, *distp = 0;
    if (OS == QN + NT + 1 + DN) {
        qp = out; indp = out + QN; lossp = out + QN + NT; distp = out + QN + NT + 1;
    } else if (OS == QN) { qp = out;
    } else if (OS == DN) { distp = out;
    } else if (OS == NT) { indp = out;
    } else if (OS == 1)  { lossp = out;
    } else if (OS == QN + NT + 1) { qp = out; indp = out + QN; lossp = out + QN + NT;
    } else {
        if (OS >= QN) qp = out;
        if (OS >= QN + NT) indp = out + QN;
        if (OS >= QN + NT + 1) lossp = out + QN + NT;
        if (OS >= QN + NT + 1 + DN) distp = out + QN + NT + 1;
    }

    cudaFuncSetAttribute(gemm_mma_kernel, cudaFuncAttributeMaxDynamicSharedMemorySize, SMEM_TOTAL);

    prep_x_kernel<<<NBY * NKB, 256>>>(X);                        // 1
    prep_e_kernel<<<NBX * NKB, 256>>>(E);                        // 2
    misc_prep_kernel<<<8352, 256>>>(X, E);                       // 3
    gemm_mma_kernel<<<dim3(NBX, NBY), 256, SMEM_TOTAL>>>(distp); // 4
    if (distp) scan_rescore_kernel<<<NT, 256>>>(X, distp);       // 5 (exact argmin)
    gather_kernel<<<NT, 128>>>(X, qp, indp);                     // 6
    if (lossp) loss_kernel<<<1, 512>>>(lossp);                   // 7
}